// round 1
// baseline (speedup 1.0000x reference)
#include <cuda_runtime.h>
#include <cuda_bf16.h>
#include <cstdint>

// Problem constants
#define NPTS   262144
#define NGRIDS 64
#define GS     64
#define CELLS  (GS*GS*GS)   // 262144 = 2^18

// Packed corner layout: for each (g, z, y, x):
//   { f0[x], f1[x], (x<63 ? f0[x+1] : 0), (x<63 ? f1[x+1] : 0) }
// One aligned float4 load fetches both features at both x-corners of a row.
__device__ float4 g_packed[(size_t)NGRIDS * CELLS];

__global__ __launch_bounds__(256) void repack_kernel(const float* __restrict__ fg)
{
    int idx = blockIdx.x * 256 + threadIdx.x;        // over NGRIDS*CELLS
    int g = idx >> 18;                                // / CELLS
    int c = idx & (CELLS - 1);
    int x = c & (GS - 1);
    const float* base = fg + (size_t)g * 2 * CELLS;   // [F=2, D, H, W]
    float f0 = base[c];
    float f1 = base[CELLS + c];
    float f0n = 0.0f, f1n = 0.0f;
    if (x < GS - 1) {
        f0n = base[c + 1];
        f1n = base[CELLS + c + 1];
    }
    g_packed[idx] = make_float4(f0, f1, f0n, f1n);
}

__global__ __launch_bounds__(256) void sample_kernel(
    const float* __restrict__ xs,     // [NPTS, 3]
    const float* __restrict__ M,      // [NGRIDS, 4, 4]
    float* __restrict__ out)          // [NPTS, NGRIDS*2]
{
    // Matrices in shared memory, pre-scaled so that
    // px = 31.5*(dot+1)  ==  sum(31.5*m_ij * t_j) + 31.5*(m_i3 + 1)
    __shared__ float sM[NGRIDS * 16];
    int tid = threadIdx.x;
    for (int i = tid; i < NGRIDS * 16; i += 256) {
        float v = M[i];
        int col = i & 3;
        v = (col == 3) ? 31.5f * (v + 1.0f) : 31.5f * v;
        sM[i] = v;
    }
    __syncthreads();

    int n = blockIdx.x * 256 + tid;
    float tx = xs[n * 3 + 0];
    float ty = xs[n * 3 + 1];
    float tz = xs[n * 3 + 2];
    float* op = out + (size_t)n * (NGRIDS * 2);

    #pragma unroll 2
    for (int g = 0; g < NGRIDS; ++g) {
        const float* m = sM + g * 16;
        float px = fmaf(m[0], tx, fmaf(m[1], ty, fmaf(m[2],  tz, m[3])));
        float py = fmaf(m[4], tx, fmaf(m[5], ty, fmaf(m[6],  tz, m[7])));
        float pz = fmaf(m[8], tx, fmaf(m[9], ty, fmaf(m[10], tz, m[11])));

        float fx0 = floorf(px), fy0 = floorf(py), fz0 = floorf(pz);
        float fx = px - fx0, fy = py - fy0, fz = pz - fz0;
        int ix = (int)fx0, iy = (int)fy0, iz = (int)fz0;

        // x weights folded onto the packed chunk:
        //  ix in [0,63]: chunk at ix, w = (1-fx, fx); slot x+1 at ix=63 holds 0.
        //  ix == -1   : chunk at 0 holds f(0) in slot0 -> w = (fx, 0).
        //  else       : both corners invalid -> (0, 0).
        bool inx = ((unsigned)ix < 64u);
        float wx0 = inx ? (1.0f - fx) : ((ix == -1) ? fx : 0.0f);
        float wx1 = inx ? fx : 0.0f;
        int ixc = min(max(ix, 0), 63);

        float wy0 = ((unsigned)iy       < 64u) ? (1.0f - fy) : 0.0f;
        float wy1 = ((unsigned)(iy + 1) < 64u) ? fy          : 0.0f;
        int iy0c = min(max(iy,     0), 63);
        int iy1c = min(max(iy + 1, 0), 63);

        float wz0 = ((unsigned)iz       < 64u) ? (1.0f - fz) : 0.0f;
        float wz1 = ((unsigned)(iz + 1) < 64u) ? fz          : 0.0f;
        int iz0c = min(max(iz,     0), 63);
        int iz1c = min(max(iz + 1, 0), 63);

        const float4* gp = g_packed + (size_t)g * CELLS;
        int r00 = (iz0c * GS + iy0c) * GS + ixc;
        int r01 = (iz0c * GS + iy1c) * GS + ixc;
        int r10 = (iz1c * GS + iy0c) * GS + ixc;
        int r11 = (iz1c * GS + iy1c) * GS + ixc;

        float4 c00 = gp[r00];
        float4 c01 = gp[r01];
        float4 c10 = gp[r10];
        float4 c11 = gp[r11];

        float w00 = wz0 * wy0;
        float w01 = wz0 * wy1;
        float w10 = wz1 * wy0;
        float w11 = wz1 * wy1;

        float s0a = fmaf(c00.x, w00, fmaf(c01.x, w01, fmaf(c10.x, w10, c11.x * w11)));
        float s0b = fmaf(c00.z, w00, fmaf(c01.z, w01, fmaf(c10.z, w10, c11.z * w11)));
        float s1a = fmaf(c00.y, w00, fmaf(c01.y, w01, fmaf(c10.y, w10, c11.y * w11)));
        float s1b = fmaf(c00.w, w00, fmaf(c01.w, w01, fmaf(c10.w, w10, c11.w * w11)));

        float acc0 = fmaf(s0a, wx0, s0b * wx1);
        float acc1 = fmaf(s1a, wx0, s1b * wx1);

        *reinterpret_cast<float2*>(op + 2 * g) = make_float2(acc0, acc1);
    }
}

extern "C" void kernel_launch(void* const* d_in, const int* in_sizes, int n_in,
                              void* d_out, int out_size)
{
    const float* xs = (const float*)d_in[0];               // [262144, 3]
    const float* M  = (const float*)d_in[1];               // [64, 4, 4]
    const float* fg = (const float*)d_in[2];               // [64, 2, 64, 64, 64]
    float* out = (float*)d_out;                             // [262144, 128]

    // Pass 1: repack feature grids into corner-pair float4 layout.
    repack_kernel<<<(NGRIDS * CELLS) / 256, 256>>>(fg);

    // Pass 2: transform + trilinear sample, one thread per point, loop grids.
    sample_kernel<<<NPTS / 256, 256>>>(xs, M, out);
}

// round 2
// speedup vs baseline: 1.6024x; 1.6024x over previous
#include <cuda_runtime.h>
#include <cuda_bf16.h>
#include <cstdint>

#define NPTS   262144
#define NGRIDS 64
#define GS     64
#define CELLS  (GS*GS*GS)     // 262144
#define GPC    4              // grids per chunk
#define NCHUNK (NGRIDS/GPC)   // 16
#define PBLK   (NPTS/256)     // 1024 point-blocks

// 32-byte chunk: features f0,f1 at (y,x),(y,x+1) in .a and (y+1,x),(y+1,x+1) in .b
struct __align__(32) Chunk { float4 a, b; };
__device__ Chunk g_pk[(size_t)NGRIDS * CELLS];   // 536 MB scratch

__device__ __forceinline__ Chunk ld256(const Chunk* p) {
    Chunk c;
    asm("ld.global.v8.f32 {%0,%1,%2,%3,%4,%5,%6,%7}, [%8];"
        : "=f"(c.a.x), "=f"(c.a.y), "=f"(c.a.z), "=f"(c.a.w),
          "=f"(c.b.x), "=f"(c.b.y), "=f"(c.b.z), "=f"(c.b.w)
        : "l"(p));
    return c;
}
__device__ __forceinline__ void st256(void* p, float4 a, float4 b) {
    asm volatile("st.global.v8.f32 [%0], {%1,%2,%3,%4,%5,%6,%7,%8};"
        :: "l"(p),
           "f"(a.x), "f"(a.y), "f"(a.z), "f"(a.w),
           "f"(b.x), "f"(b.y), "f"(b.z), "f"(b.w)
        : "memory");
}

__global__ __launch_bounds__(256) void repack_kernel(const float* __restrict__ fg)
{
    int idx = blockIdx.x * 256 + threadIdx.x;          // over NGRIDS*CELLS
    int g = idx >> 18;
    int c = idx & (CELLS - 1);
    int x = c & (GS - 1);
    int y = (c >> 6) & (GS - 1);
    const float* base = fg + (size_t)g * 2 * CELLS;    // [F=2, D, H, W]
    bool xv = (x < GS - 1);
    bool yv = (y < GS - 1);

    float4 a, b;
    a.x = base[c];
    a.y = base[CELLS + c];
    a.z = xv ? base[c + 1] : 0.0f;
    a.w = xv ? base[CELLS + c + 1] : 0.0f;
    b.x = yv ? base[c + GS] : 0.0f;
    b.y = yv ? base[CELLS + c + GS] : 0.0f;
    b.z = (xv && yv) ? base[c + GS + 1] : 0.0f;
    b.w = (xv && yv) ? base[CELLS + c + GS + 1] : 0.0f;

    st256(&g_pk[idx], a, b);
}

__global__ __launch_bounds__(256) void sample_kernel(
    const float* __restrict__ xs,     // [NPTS, 3]
    const float* __restrict__ M,      // [NGRIDS, 4, 4]
    float* __restrict__ out)          // [NPTS, NGRIDS*2]
{
    __shared__ float sM[NGRIDS * 16];
    int tid = threadIdx.x;
    for (int i = tid; i < NGRIDS * 16; i += 256) {
        float v = M[i];
        int col = i & 3;
        sM[i] = (col == 3) ? 31.5f * (v + 1.0f) : 31.5f * v;
    }
    __syncthreads();

    int chunk = blockIdx.x >> 10;        // grid-chunk (slow-varying -> L2 locality)
    int pb    = blockIdx.x & (PBLK - 1);
    int n = pb * 256 + tid;

    float tx = xs[n * 3 + 0];
    float ty = xs[n * 3 + 1];
    float tz = xs[n * 3 + 2];

    float res[8];

    #pragma unroll
    for (int j = 0; j < GPC; ++j) {
        int g = chunk * GPC + j;
        const float* m = sM + g * 16;
        float px = fmaf(m[0], tx, fmaf(m[1], ty, fmaf(m[2],  tz, m[3])));
        float py = fmaf(m[4], tx, fmaf(m[5], ty, fmaf(m[6],  tz, m[7])));
        float pz = fmaf(m[8], tx, fmaf(m[9], ty, fmaf(m[10], tz, m[11])));

        float fx0 = floorf(px), fy0 = floorf(py), fz0 = floorf(pz);
        float fx = px - fx0, fy = py - fy0, fz = pz - fz0;
        int ix = (int)fx0, iy = (int)fy0, iz = (int)fz0;

        // x folded into chunk slots (slot x+1 at x=63 stores 0)
        bool inx = ((unsigned)ix < 64u);
        float wx0 = inx ? (1.0f - fx) : ((ix == -1) ? fx : 0.0f);
        float wx1 = inx ? fx : 0.0f;
        int ixc = min(max(ix, 0), 63);

        // y folded into chunk slots (slot y+1 at y=63 stores 0)
        bool iny = ((unsigned)iy < 64u);
        float wyA = iny ? (1.0f - fy) : ((iy == -1) ? fy : 0.0f);
        float wyB = iny ? fy : 0.0f;
        int iyc = min(max(iy, 0), 63);

        // z: plain masking, two gathers
        float wz0 = ((unsigned)iz       < 64u) ? (1.0f - fz) : 0.0f;
        float wz1 = ((unsigned)(iz + 1) < 64u) ? fz          : 0.0f;
        int iz0c = min(max(iz,     0), 63);
        int iz1c = min(max(iz + 1, 0), 63);

        const Chunk* gp = g_pk + (size_t)g * CELLS;
        int c0 = (iz0c * GS + iyc) * GS + ixc;
        int c1 = (iz1c * GS + iyc) * GS + ixc;

        Chunk u = ld256(gp + c0);
        Chunk v = ld256(gp + c1);

        // per-z bilinear in (x,y), per feature
        float e00 = fmaf(wyA, fmaf(u.a.x, wx0, u.a.z * wx1),
                         wyB * fmaf(u.b.x, wx0, u.b.z * wx1));   // z0, f0
        float e01 = fmaf(wyA, fmaf(u.a.y, wx0, u.a.w * wx1),
                         wyB * fmaf(u.b.y, wx0, u.b.w * wx1));   // z0, f1
        float e10 = fmaf(wyA, fmaf(v.a.x, wx0, v.a.z * wx1),
                         wyB * fmaf(v.b.x, wx0, v.b.z * wx1));   // z1, f0
        float e11 = fmaf(wyA, fmaf(v.a.y, wx0, v.a.w * wx1),
                         wyB * fmaf(v.b.y, wx0, v.b.w * wx1));   // z1, f1

        res[2 * j]     = fmaf(wz0, e00, wz1 * e10);
        res[2 * j + 1] = fmaf(wz0, e01, wz1 * e11);
    }

    float* op = out + (size_t)n * (NGRIDS * 2) + chunk * (GPC * 2);
    st256(op, make_float4(res[0], res[1], res[2], res[3]),
              make_float4(res[4], res[5], res[6], res[7]));
}

extern "C" void kernel_launch(void* const* d_in, const int* in_sizes, int n_in,
                              void* d_out, int out_size)
{
    const float* xs = (const float*)d_in[0];   // [262144, 3]
    const float* M  = (const float*)d_in[1];   // [64, 4, 4]
    const float* fg = (const float*)d_in[2];   // [64, 2, 64, 64, 64]
    float* out = (float*)d_out;                // [262144, 128]

    repack_kernel<<<(NGRIDS * CELLS) / 256, 256>>>(fg);
    sample_kernel<<<NCHUNK * PBLK, 256>>>(xs, M, out);
}

// round 3
// speedup vs baseline: 1.9325x; 1.2060x over previous
#include <cuda_runtime.h>
#include <cuda_fp16.h>
#include <cstdint>

#define NPTS   262144
#define NGRIDS 64
#define GS     64
#define CELLS  (GS*GS*GS)     // 262144
#define GPC    4              // grids per chunk (L2 working set = 4 * 8.4MB)
#define NCHUNK (NGRIDS/GPC)   // 16
#define PBLK   (NPTS/256)     // 1024 point-blocks
#define FSCALE 16384.0f
#define FINV   (1.0f/16384.0f)

// 32-byte chunk per (g,z,y,x): 8 half2, one per corner k = dz*4+dy*2+dx,
// each half2 = (f0, f1) scaled by FSCALE. Out-of-range (+1 at 63) slots = 0.
struct __align__(32) Chunk { unsigned r[8]; };
__device__ Chunk g_pk[(size_t)NGRIDS * CELLS];   // 536 MB scratch

__device__ __forceinline__ void st256cs(void* p, const unsigned* r) {
    asm volatile("st.global.cs.v8.b32 [%0], {%1,%2,%3,%4,%5,%6,%7,%8};"
        :: "l"(p), "r"(r[0]), "r"(r[1]), "r"(r[2]), "r"(r[3]),
           "r"(r[4]), "r"(r[5]), "r"(r[6]), "r"(r[7]) : "memory");
}
__device__ __forceinline__ void st256cs_f(void* p, const float* f) {
    asm volatile("st.global.cs.v8.f32 [%0], {%1,%2,%3,%4,%5,%6,%7,%8};"
        :: "l"(p), "f"(f[0]), "f"(f[1]), "f"(f[2]), "f"(f[3]),
           "f"(f[4]), "f"(f[5]), "f"(f[6]), "f"(f[7]) : "memory");
}
__device__ __forceinline__ void ld256nc(const void* p, unsigned* r) {
    asm("ld.global.nc.v8.b32 {%0,%1,%2,%3,%4,%5,%6,%7}, [%8];"
        : "=r"(r[0]), "=r"(r[1]), "=r"(r[2]), "=r"(r[3]),
          "=r"(r[4]), "=r"(r[5]), "=r"(r[6]), "=r"(r[7]) : "l"(p));
}

__global__ __launch_bounds__(256) void repack_kernel(const float* __restrict__ fg)
{
    int idx = blockIdx.x * 256 + threadIdx.x;          // over NGRIDS*CELLS
    int g = idx >> 18;
    int c = idx & (CELLS - 1);
    int x = c & (GS - 1);
    int y = (c >> 6) & (GS - 1);
    int z = c >> 12;
    const float* base = fg + (size_t)g * 2 * CELLS;    // [F=2, D, H, W]

    unsigned r[8];
    #pragma unroll
    for (int k = 0; k < 8; ++k) {
        int dz = k >> 2, dy = (k >> 1) & 1, dx = k & 1;
        bool valid = (x + dx < GS) && (y + dy < GS) && (z + dz < GS);
        int off = c + dz * 4096 + dy * 64 + dx;
        float v0 = valid ? base[off] : 0.0f;
        float v1 = valid ? base[CELLS + off] : 0.0f;
        __half2 h = __floats2half2_rn(v0 * FSCALE, v1 * FSCALE);
        r[k] = *reinterpret_cast<unsigned*>(&h);
    }
    st256cs(&g_pk[idx], r);
}

__global__ __launch_bounds__(256) void sample_kernel(
    const float* __restrict__ xs,     // [NPTS, 3]
    const float* __restrict__ M,      // [NGRIDS, 4, 4]
    float* __restrict__ out)          // [NPTS, NGRIDS*2]
{
    __shared__ float sM[NGRIDS * 16];
    int tid = threadIdx.x;
    for (int i = tid; i < NGRIDS * 16; i += 256) {
        float v = M[i];
        int col = i & 3;
        sM[i] = (col == 3) ? 31.5f * (v + 1.0f) : 31.5f * v;
    }
    __syncthreads();

    int chunk = blockIdx.x >> 10;        // slow-varying -> L2-resident grid slab
    int pb    = blockIdx.x & (PBLK - 1);
    int n = pb * 256 + tid;

    float tx = xs[n * 3 + 0];
    float ty = xs[n * 3 + 1];
    float tz = xs[n * 3 + 2];

    float res[8];

    #pragma unroll
    for (int j = 0; j < GPC; ++j) {
        int g = chunk * GPC + j;
        const float* m = sM + g * 16;
        float px = fmaf(m[0], tx, fmaf(m[1], ty, fmaf(m[2],  tz, m[3])));
        float py = fmaf(m[4], tx, fmaf(m[5], ty, fmaf(m[6],  tz, m[7])));
        float pz = fmaf(m[8], tx, fmaf(m[9], ty, fmaf(m[10], tz, m[11])));

        float fx0 = floorf(px), fy0 = floorf(py), fz0 = floorf(pz);
        float fx = px - fx0, fy = py - fy0, fz = pz - fz0;
        int ix = (int)fx0, iy = (int)fy0, iz = (int)fz0;

        // Per-dim: slot +1 at coord 63 stores 0, so clamping + weight folding
        // handles all boundary cases (incl. coord == -1 mapping to slot 0).
        bool inx = ((unsigned)ix < 64u);
        float wx0 = inx ? (1.0f - fx) : ((ix == -1) ? fx : 0.0f);
        float wx1 = inx ? fx : 0.0f;
        int xc = min(max(ix, 0), 63);

        bool iny = ((unsigned)iy < 64u);
        float wy0 = iny ? (1.0f - fy) : ((iy == -1) ? fy : 0.0f);
        float wy1 = iny ? fy : 0.0f;
        int yc = min(max(iy, 0), 63);

        bool inz = ((unsigned)iz < 64u);
        float wz0 = inz ? (1.0f - fz) : ((iz == -1) ? fz : 0.0f);
        float wz1 = inz ? fz : 0.0f;
        int zc = min(max(iz, 0), 63);
        wz0 *= FINV;  // fold fp16 scale removal into z weights
        wz1 *= FINV;

        const Chunk* gp = g_pk + (size_t)g * CELLS;
        unsigned r[8];
        ld256nc(gp + ((zc * GS + yc) * GS + xc), r);

        float w00 = wz0 * wy0, w01 = wz0 * wy1;
        float w10 = wz1 * wy0, w11 = wz1 * wy1;
        float wgt[8] = { w00 * wx0, w00 * wx1, w01 * wx0, w01 * wx1,
                         w10 * wx0, w10 * wx1, w11 * wx0, w11 * wx1 };

        float a0 = 0.0f, a1 = 0.0f;
        #pragma unroll
        for (int k = 0; k < 8; ++k) {
            __half2 h = *reinterpret_cast<__half2*>(&r[k]);
            float2 v = __half22float2(h);
            a0 = fmaf(v.x, wgt[k], a0);
            a1 = fmaf(v.y, wgt[k], a1);
        }
        res[2 * j]     = a0;
        res[2 * j + 1] = a1;
    }

    float* op = out + (size_t)n * (NGRIDS * 2) + chunk * (GPC * 2);
    st256cs_f(op, res);
}

extern "C" void kernel_launch(void* const* d_in, const int* in_sizes, int n_in,
                              void* d_out, int out_size)
{
    const float* xs = (const float*)d_in[0];   // [262144, 3]
    const float* M  = (const float*)d_in[1];   // [64, 4, 4]
    const float* fg = (const float*)d_in[2];   // [64, 2, 64, 64, 64]
    float* out = (float*)d_out;                // [262144, 128]

    repack_kernel<<<(NGRIDS * CELLS) / 256, 256>>>(fg);
    sample_kernel<<<NCHUNK * PBLK, 256>>>(xs, M, out);
}

// round 4
// speedup vs baseline: 2.1882x; 1.1324x over previous
#include <cuda_runtime.h>
#include <cuda_fp16.h>
#include <cstdint>

#define NPTS   262144
#define NGRIDS 64
#define GS     64
#define CELLS  (GS*GS*GS)     // 262144
#define GPC    4              // grids per chunk (L2 slab = 4 * 4.2MB)
#define NCHUNK (NGRIDS/GPC)   // 16
#define PBLK   (NPTS/256)     // 1024 point-blocks
#define FSCALE 16384.0f
#define FINV   (1.0f/16384.0f)

// 16-byte chunk per (g,z,y,x): 4 half2, slot k = dy*2+dx holds (f0,f1)*FSCALE
// at (z, y+dy, x+dx). Slots past the 63-edge hold 0.
struct __align__(16) Chunk { unsigned r[4]; };
__device__ Chunk g_pk[(size_t)NGRIDS * CELLS];   // 268 MB scratch

__device__ __forceinline__ void st128cs(void* p, const unsigned* r) {
    asm volatile("st.global.cs.v4.b32 [%0], {%1,%2,%3,%4};"
        :: "l"(p), "r"(r[0]), "r"(r[1]), "r"(r[2]), "r"(r[3]) : "memory");
}
__device__ __forceinline__ void st256cs_f(void* p, const float* f) {
    asm volatile("st.global.cs.v8.f32 [%0], {%1,%2,%3,%4,%5,%6,%7,%8};"
        :: "l"(p), "f"(f[0]), "f"(f[1]), "f"(f[2]), "f"(f[3]),
           "f"(f[4]), "f"(f[5]), "f"(f[6]), "f"(f[7]) : "memory");
}
__device__ __forceinline__ void ld128nc(const void* p, unsigned* r) {
    asm("ld.global.nc.v4.b32 {%0,%1,%2,%3}, [%4];"
        : "=r"(r[0]), "=r"(r[1]), "=r"(r[2]), "=r"(r[3]) : "l"(p));
}

__global__ __launch_bounds__(256) void repack_kernel(const float* __restrict__ fg)
{
    int idx = blockIdx.x * 256 + threadIdx.x;          // over NGRIDS*CELLS
    int g = idx >> 18;
    int c = idx & (CELLS - 1);
    int x = c & (GS - 1);
    int y = (c >> 6) & (GS - 1);
    const float* base = fg + (size_t)g * 2 * CELLS;    // [F=2, D, H, W]

    unsigned r[4];
    #pragma unroll
    for (int k = 0; k < 4; ++k) {
        int dy = k >> 1, dx = k & 1;
        bool valid = (x + dx < GS) && (y + dy < GS);
        int off = c + dy * GS + dx;
        float v0 = valid ? base[off] : 0.0f;
        float v1 = valid ? base[CELLS + off] : 0.0f;
        __half2 h = __floats2half2_rn(v0 * FSCALE, v1 * FSCALE);
        r[k] = *reinterpret_cast<unsigned*>(&h);
    }
    st128cs(&g_pk[idx], r);
}

__global__ __launch_bounds__(256) void sample_kernel(
    const float* __restrict__ xs,     // [NPTS, 3]
    const float* __restrict__ M,      // [NGRIDS, 4, 4]
    float* __restrict__ out)          // [NPTS, NGRIDS*2]
{
    __shared__ float sM[NGRIDS * 16];
    int tid = threadIdx.x;
    for (int i = tid; i < NGRIDS * 16; i += 256) {
        float v = M[i];
        int col = i & 3;
        sM[i] = (col == 3) ? 31.5f * (v + 1.0f) : 31.5f * v;
    }
    __syncthreads();

    int chunk = blockIdx.x >> 10;        // slow-varying -> L2-resident grid slab
    int pb    = blockIdx.x & (PBLK - 1);
    int n = pb * 256 + tid;

    float tx = xs[n * 3 + 0];
    float ty = xs[n * 3 + 1];
    float tz = xs[n * 3 + 2];

    float res[8];

    #pragma unroll
    for (int j = 0; j < GPC; ++j) {
        int g = chunk * GPC + j;
        const float* m = sM + g * 16;
        float px = fmaf(m[0], tx, fmaf(m[1], ty, fmaf(m[2],  tz, m[3])));
        float py = fmaf(m[4], tx, fmaf(m[5], ty, fmaf(m[6],  tz, m[7])));
        float pz = fmaf(m[8], tx, fmaf(m[9], ty, fmaf(m[10], tz, m[11])));

        float fx0 = floorf(px), fy0 = floorf(py), fz0 = floorf(pz);
        float fx = px - fx0, fy = py - fy0, fz = pz - fz0;
        int ix = (int)fx0, iy = (int)fy0, iz = (int)fz0;

        // x,y folded into chunk slots (slot +1 at 63 stores 0; coord==-1 maps
        // to slot 0 with swapped weight). z: two plane loads, masked weights.
        bool inx = ((unsigned)ix < 64u);
        float wx0 = inx ? (1.0f - fx) : ((ix == -1) ? fx : 0.0f);
        float wx1 = inx ? fx : 0.0f;
        int xc = min(max(ix, 0), 63);

        bool iny = ((unsigned)iy < 64u);
        float wy0 = iny ? (1.0f - fy) : ((iy == -1) ? fy : 0.0f);
        float wy1 = iny ? fy : 0.0f;
        int yc = min(max(iy, 0), 63);

        float wz0 = ((unsigned)iz       < 64u) ? (1.0f - fz) * FINV : 0.0f;
        float wz1 = ((unsigned)(iz + 1) < 64u) ? fz          * FINV : 0.0f;
        int iz0c = min(max(iz,     0), 63);
        int iz1c = min(max(iz + 1, 0), 63);

        const Chunk* gp = g_pk + (size_t)g * CELLS;
        unsigned u[4], v[4];
        ld128nc(gp + ((iz0c * GS + yc) * GS + xc), u);
        ld128nc(gp + ((iz1c * GS + yc) * GS + xc), v);

        float wgt[4] = { wy0 * wx0, wy0 * wx1, wy1 * wx0, wy1 * wx1 };

        float a0 = 0.0f, a1 = 0.0f;
        #pragma unroll
        for (int k = 0; k < 4; ++k) {
            float2 uu = __half22float2(*reinterpret_cast<__half2*>(&u[k]));
            float2 vv = __half22float2(*reinterpret_cast<__half2*>(&v[k]));
            float wk0 = wgt[k] * wz0;
            float wk1 = wgt[k] * wz1;
            a0 = fmaf(uu.x, wk0, fmaf(vv.x, wk1, a0));
            a1 = fmaf(uu.y, wk0, fmaf(vv.y, wk1, a1));
        }
        res[2 * j]     = a0;
        res[2 * j + 1] = a1;
    }

    float* op = out + (size_t)n * (NGRIDS * 2) + chunk * (GPC * 2);
    st256cs_f(op, res);
}

extern "C" void kernel_launch(void* const* d_in, const int* in_sizes, int n_in,
                              void* d_out, int out_size)
{
    const float* xs = (const float*)d_in[0];   // [262144, 3]
    const float* M  = (const float*)d_in[1];   // [64, 4, 4]
    const float* fg = (const float*)d_in[2];   // [64, 2, 64, 64, 64]
    float* out = (float*)d_out;                // [262144, 128]

    repack_kernel<<<(NGRIDS * CELLS) / 256, 256>>>(fg);
    sample_kernel<<<NCHUNK * PBLK, 256>>>(xs, M, out);
}

// round 6
// speedup vs baseline: 2.5345x; 1.1582x over previous
#include <cuda_runtime.h>
#include <cuda_fp16.h>
#include <cstdint>

#define NPTS   262144
#define NGRIDS 64
#define GS     64
#define CELLS  (GS*GS*GS)     // 262144
#define GPC    4              // grids per epoch (slab = 4 * 4.2MB, L2-resident)
#define NCHUNK (NGRIDS/GPC)   // 16
#define PBLK   (NPTS/256)     // 1024
#define NBINS  262144         // 64^3 spatial bins == grid cells
#define FSCALE 16384.0f
#define FINV   (1.0f/16384.0f)

// 16-byte chunk per (g,z,y,x): 4 half2, slot k = dy*2+dx = (f0,f1)*FSCALE
// at (z, y+dy, x+dx); slots past the 63-edge hold 0.
struct __align__(16) Chunk { unsigned r[4]; };
__device__ Chunk  g_pk[(size_t)NGRIDS * CELLS];   // 268 MB scratch
__device__ int    g_hist[NBINS];
__device__ int    g_binStart[NBINS];
__device__ int    g_bsum[1024];
__device__ float4 g_pxs[NPTS];   // sorted points: (x, y, z, bitcast(orig idx))

__device__ __forceinline__ void st128cs(void* p, const unsigned* r) {
    asm volatile("st.global.cs.v4.b32 [%0], {%1,%2,%3,%4};"
        :: "l"(p), "r"(r[0]), "r"(r[1]), "r"(r[2]), "r"(r[3]) : "memory");
}
__device__ __forceinline__ void st256cs_f(void* p, const float* f) {
    asm volatile("st.global.cs.v8.f32 [%0], {%1,%2,%3,%4,%5,%6,%7,%8};"
        :: "l"(p), "f"(f[0]), "f"(f[1]), "f"(f[2]), "f"(f[3]),
           "f"(f[4]), "f"(f[5]), "f"(f[6]), "f"(f[7]) : "memory");
}
__device__ __forceinline__ void ld128nc(const void* p, unsigned* r) {
    asm("ld.global.nc.v4.b32 {%0,%1,%2,%3}, [%4];"
        : "=r"(r[0]), "=r"(r[1]), "=r"(r[2]), "=r"(r[3]) : "l"(p));
}

__device__ __forceinline__ int point_key(float tx, float ty, float tz) {
    int qx = min(max((int)((tx + 1.0f) * 32.0f), 0), 63);
    int qy = min(max((int)((ty + 1.0f) * 32.0f), 0), 63);
    int qz = min(max((int)((tz + 1.0f) * 32.0f), 0), 63);
    return (qz * GS + qy) * GS + qx;   // x fastest (matches chunk layout)
}

// ---------------- sort pipeline ----------------
__global__ __launch_bounds__(256) void zero_kernel() {
    g_hist[blockIdx.x * 256 + threadIdx.x] = 0;
}
__global__ __launch_bounds__(256) void hist_kernel(const float* __restrict__ xs) {
    int n = blockIdx.x * 256 + threadIdx.x;
    atomicAdd(&g_hist[point_key(xs[n*3], xs[n*3+1], xs[n*3+2])], 1);
}
__global__ __launch_bounds__(256) void scan1_kernel() {
    __shared__ int s[256];
    int t = threadIdx.x;
    s[t] = g_hist[blockIdx.x * 256 + t];
    __syncthreads();
    for (int o = 128; o > 0; o >>= 1) {
        if (t < o) s[t] += s[t + o];
        __syncthreads();
    }
    if (t == 0) g_bsum[blockIdx.x] = s[0];
}
__global__ __launch_bounds__(1024) void scan2_kernel() {
    __shared__ int s[1024];
    int t = threadIdx.x;
    int v = g_bsum[t];
    s[t] = v;
    __syncthreads();
    for (int o = 1; o < 1024; o <<= 1) {
        int x = (t >= o) ? s[t - o] : 0;
        __syncthreads();
        s[t] += x;
        __syncthreads();
    }
    g_bsum[t] = s[t] - v;   // exclusive
}
__global__ __launch_bounds__(256) void scan3_kernel() {
    __shared__ int s[256];
    int t = threadIdx.x;
    int i = blockIdx.x * 256 + t;
    int v = g_hist[i];
    s[t] = v;
    __syncthreads();
    for (int o = 1; o < 256; o <<= 1) {
        int x = (t >= o) ? s[t - o] : 0;
        __syncthreads();
        s[t] += x;
        __syncthreads();
    }
    g_binStart[i] = s[t] - v + g_bsum[blockIdx.x];
}
__global__ __launch_bounds__(256) void scatter_kernel(const float* __restrict__ xs) {
    int n = blockIdx.x * 256 + threadIdx.x;
    float tx = xs[n*3], ty = xs[n*3+1], tz = xs[n*3+2];
    int pos = atomicAdd(&g_binStart[point_key(tx, ty, tz)], 1);
    g_pxs[pos] = make_float4(tx, ty, tz, __int_as_float(n));
}

// ---------------- repack (fp16 2x2 xy-patch chunks) ----------------
__global__ __launch_bounds__(256) void repack_kernel(const float* __restrict__ fg)
{
    int idx = blockIdx.x * 256 + threadIdx.x;          // over NGRIDS*CELLS
    int g = idx >> 18;
    int c = idx & (CELLS - 1);
    int x = c & (GS - 1);
    int y = (c >> 6) & (GS - 1);
    const float* base = fg + (size_t)g * 2 * CELLS;    // [F=2, D, H, W]

    unsigned r[4];
    #pragma unroll
    for (int k = 0; k < 4; ++k) {
        int dy = k >> 1, dx = k & 1;
        bool valid = (x + dx < GS) && (y + dy < GS);
        int off = c + dy * GS + dx;
        float v0 = valid ? base[off] : 0.0f;
        float v1 = valid ? base[CELLS + off] : 0.0f;
        __half2 h = __floats2half2_rn(v0 * FSCALE, v1 * FSCALE);
        r[k] = *reinterpret_cast<unsigned*>(&h);
    }
    st128cs(&g_pk[idx], r);
}

// ---------------- sample ----------------
__global__ __launch_bounds__(256) void sample_kernel(
    const float* __restrict__ M,      // [64, 4, 4]
    float* __restrict__ out)          // [NPTS, 128]
{
    __shared__ float sM[NGRIDS * 16];
    int tid = threadIdx.x;
    for (int i = tid; i < NGRIDS * 16; i += 256) {
        float v = M[i];
        sM[i] = ((i & 3) == 3) ? 31.5f * (v + 1.0f) : 31.5f * v;
    }
    __syncthreads();

    int chunk = blockIdx.x >> 10;              // grid epoch (L2-resident slab)
    int t     = (blockIdx.x & (PBLK - 1)) * 256 + tid;

    float4 p = g_pxs[t];                       // sorted -> warp-coherent gathers
    float tx = p.x, ty = p.y, tz = p.z;
    int n = __float_as_int(p.w);

    float res[8];

    #pragma unroll
    for (int j = 0; j < GPC; ++j) {
        int g = chunk * GPC + j;
        const float* m = sM + g * 16;
        float px = fmaf(m[0], tx, fmaf(m[1], ty, fmaf(m[2],  tz, m[3])));
        float py = fmaf(m[4], tx, fmaf(m[5], ty, fmaf(m[6],  tz, m[7])));
        float pz = fmaf(m[8], tx, fmaf(m[9], ty, fmaf(m[10], tz, m[11])));

        float fx0 = floorf(px), fy0 = floorf(py), fz0 = floorf(pz);
        float fx = px - fx0, fy = py - fy0, fz = pz - fz0;
        int ix = (int)fx0, iy = (int)fy0, iz = (int)fz0;

        // x,y folded into chunk slots (slot +1 at 63 stores 0; coord==-1 maps
        // to slot 0 with swapped weight). z: two plane loads, masked weights.
        bool inx = ((unsigned)ix < 64u);
        float wx0 = inx ? (1.0f - fx) : ((ix == -1) ? fx : 0.0f);
        float wx1 = inx ? fx : 0.0f;
        int xc = min(max(ix, 0), 63);

        bool iny = ((unsigned)iy < 64u);
        float wy0 = iny ? (1.0f - fy) : ((iy == -1) ? fy : 0.0f);
        float wy1 = iny ? fy : 0.0f;
        int yc = min(max(iy, 0), 63);

        float wz0 = ((unsigned)iz       < 64u) ? (1.0f - fz) * FINV : 0.0f;
        float wz1 = ((unsigned)(iz + 1) < 64u) ? fz          * FINV : 0.0f;
        int iz0c = min(max(iz,     0), 63);
        int iz1c = min(max(iz + 1, 0), 63);

        const Chunk* gp = g_pk + (size_t)g * CELLS;
        unsigned u[4], v[4];
        ld128nc(gp + ((iz0c * GS + yc) * GS + xc), u);
        ld128nc(gp + ((iz1c * GS + yc) * GS + xc), v);

        float wgt[4] = { wy0 * wx0, wy0 * wx1, wy1 * wx0, wy1 * wx1 };

        float a0 = 0.0f, a1 = 0.0f;
        #pragma unroll
        for (int k = 0; k < 4; ++k) {
            float2 uu = __half22float2(*reinterpret_cast<__half2*>(&u[k]));
            float2 vv = __half22float2(*reinterpret_cast<__half2*>(&v[k]));
            float wk0 = wgt[k] * wz0;
            float wk1 = wgt[k] * wz1;
            a0 = fmaf(uu.x, wk0, fmaf(vv.x, wk1, a0));
            a1 = fmaf(uu.y, wk0, fmaf(vv.y, wk1, a1));
        }
        res[2 * j]     = a0;
        res[2 * j + 1] = a1;
    }

    float* op = out + (size_t)n * (NGRIDS * 2) + chunk * (GPC * 2);
    st256cs_f(op, res);
}

extern "C" void kernel_launch(void* const* d_in, const int* in_sizes, int n_in,
                              void* d_out, int out_size)
{
    const float* xs = (const float*)d_in[0];   // [262144, 3]
    const float* M  = (const float*)d_in[1];   // [64, 4, 4]
    const float* fg = (const float*)d_in[2];   // [64, 2, 64, 64, 64]
    float* out = (float*)d_out;                // [262144, 128]

    zero_kernel   <<<NBINS / 256, 256>>>();
    hist_kernel   <<<NPTS / 256, 256>>>(xs);
    scan1_kernel  <<<NBINS / 256, 256>>>();
    scan2_kernel  <<<1, 1024>>>();
    scan3_kernel  <<<NBINS / 256, 256>>>();
    scatter_kernel<<<NPTS / 256, 256>>>(xs);
    repack_kernel <<<(NGRIDS * CELLS) / 256, 256>>>(fg);
    sample_kernel <<<NCHUNK * PBLK, 256>>>(M, out);
}

// round 7
// speedup vs baseline: 2.7549x; 1.0869x over previous
#include <cuda_runtime.h>
#include <cuda_fp16.h>
#include <cstdint>

#define NPTS   262144
#define NGRIDS 64
#define GS     64
#define CELLS  (GS*GS*GS)     // 262144
#define GPC    8              // grids per epoch (slab = 8 * 2.1MB, L2-resident)
#define NCHUNK (NGRIDS/GPC)   // 8
#define PBLK   (NPTS/256)     // 1024
#define NBINS  262144         // 64^3 spatial bins == grid cells
#define FSCALE 16384.0f
#define FINV   (1.0f/16384.0f)

// 8-byte chunk per (g,z,y,x): slot0 = half2(f0[x],f1[x])*FSCALE,
// slot1 = half2(f0[x+1],f1[x+1])*FSCALE (0 past the 63-edge).
__device__ uint2  g_pk[(size_t)NGRIDS * CELLS];   // 134 MB scratch
__device__ int    g_hist[NBINS];
__device__ int    g_binStart[NBINS];
__device__ int    g_bsum[1024];
__device__ float4 g_pxs[NPTS];   // sorted points: (x, y, z, bitcast(orig idx))

__device__ __forceinline__ void st64cs(void* p, uint2 v) {
    asm volatile("st.global.cs.v2.b32 [%0], {%1,%2};"
        :: "l"(p), "r"(v.x), "r"(v.y) : "memory");
}
__device__ __forceinline__ uint2 ld64nc(const void* p) {
    uint2 v;
    asm("ld.global.nc.v2.b32 {%0,%1}, [%2];" : "=r"(v.x), "=r"(v.y) : "l"(p));
    return v;
}
__device__ __forceinline__ void st256cs_f(void* p, const float* f) {
    asm volatile("st.global.cs.v8.f32 [%0], {%1,%2,%3,%4,%5,%6,%7,%8};"
        :: "l"(p), "f"(f[0]), "f"(f[1]), "f"(f[2]), "f"(f[3]),
           "f"(f[4]), "f"(f[5]), "f"(f[6]), "f"(f[7]) : "memory");
}

__device__ __forceinline__ int point_key(float tx, float ty, float tz) {
    int qx = min(max((int)((tx + 1.0f) * 32.0f), 0), 63);
    int qy = min(max((int)((ty + 1.0f) * 32.0f), 0), 63);
    int qz = min(max((int)((tz + 1.0f) * 32.0f), 0), 63);
    return (qz * GS + qy) * GS + qx;   // x fastest (matches chunk layout)
}

// ---------------- sort pipeline ----------------
__global__ __launch_bounds__(256) void zero_kernel() {
    g_hist[blockIdx.x * 256 + threadIdx.x] = 0;
}
__global__ __launch_bounds__(256) void hist_kernel(const float* __restrict__ xs) {
    int n = blockIdx.x * 256 + threadIdx.x;
    atomicAdd(&g_hist[point_key(xs[n*3], xs[n*3+1], xs[n*3+2])], 1);
}
__global__ __launch_bounds__(256) void scan1_kernel() {
    __shared__ int s[256];
    int t = threadIdx.x;
    s[t] = g_hist[blockIdx.x * 256 + t];
    __syncthreads();
    for (int o = 128; o > 0; o >>= 1) {
        if (t < o) s[t] += s[t + o];
        __syncthreads();
    }
    if (t == 0) g_bsum[blockIdx.x] = s[0];
}
// exclusive scan of 1024 totals, shfl-based
__global__ __launch_bounds__(1024) void scan2_kernel() {
    __shared__ int ws[32];
    int t = threadIdx.x;
    int lane = t & 31, w = t >> 5;
    int v = g_bsum[t];
    int s = v;
    #pragma unroll
    for (int o = 1; o < 32; o <<= 1) {
        int x = __shfl_up_sync(0xffffffffu, s, o);
        if (lane >= o) s += x;
    }
    if (lane == 31) ws[w] = s;
    __syncthreads();
    if (w == 0) {
        int y = ws[lane];
        #pragma unroll
        for (int o = 1; o < 32; o <<= 1) {
            int x = __shfl_up_sync(0xffffffffu, y, o);
            if (lane >= o) y += x;
        }
        ws[lane] = y;
    }
    __syncthreads();
    int off = (w > 0) ? ws[w - 1] : 0;
    g_bsum[t] = off + s - v;   // exclusive
}
__global__ __launch_bounds__(256) void scan3_kernel() {
    __shared__ int s[256];
    int t = threadIdx.x;
    int i = blockIdx.x * 256 + t;
    int v = g_hist[i];
    s[t] = v;
    __syncthreads();
    for (int o = 1; o < 256; o <<= 1) {
        int x = (t >= o) ? s[t - o] : 0;
        __syncthreads();
        s[t] += x;
        __syncthreads();
    }
    g_binStart[i] = s[t] - v + g_bsum[blockIdx.x];
}
__global__ __launch_bounds__(256) void scatter_kernel(const float* __restrict__ xs) {
    int n = blockIdx.x * 256 + threadIdx.x;
    float tx = xs[n*3], ty = xs[n*3+1], tz = xs[n*3+2];
    int pos = atomicAdd(&g_binStart[point_key(tx, ty, tz)], 1);
    g_pxs[pos] = make_float4(tx, ty, tz, __int_as_float(n));
}

// ---------------- repack (fp16 x-pair chunks, 8B) ----------------
__global__ __launch_bounds__(256) void repack_kernel(const float* __restrict__ fg)
{
    int idx = blockIdx.x * 256 + threadIdx.x;          // over NGRIDS*CELLS
    int g = idx >> 18;
    int c = idx & (CELLS - 1);
    int x = c & (GS - 1);
    const float* base = fg + (size_t)g * 2 * CELLS;    // [F=2, D, H, W]

    float a0 = base[c];
    float a1 = base[CELLS + c];
    float b0 = 0.0f, b1 = 0.0f;
    if (x < GS - 1) {
        b0 = base[c + 1];
        b1 = base[CELLS + c + 1];
    }
    __half2 h0 = __floats2half2_rn(a0 * FSCALE, a1 * FSCALE);
    __half2 h1 = __floats2half2_rn(b0 * FSCALE, b1 * FSCALE);
    uint2 v;
    v.x = *reinterpret_cast<unsigned*>(&h0);
    v.y = *reinterpret_cast<unsigned*>(&h1);
    st64cs(&g_pk[idx], v);
}

// ---------------- sample ----------------
__global__ __launch_bounds__(256) void sample_kernel(
    const float* __restrict__ M,      // [64, 4, 4]
    float* __restrict__ out)          // [NPTS, 128]
{
    __shared__ float sM[NGRIDS * 16];
    int tid = threadIdx.x;
    for (int i = tid; i < NGRIDS * 16; i += 256) {
        float v = M[i];
        sM[i] = ((i & 3) == 3) ? 31.5f * (v + 1.0f) : 31.5f * v;
    }
    __syncthreads();

    int chunk = blockIdx.x >> 10;              // grid epoch (L2-resident slab)
    int t     = (blockIdx.x & (PBLK - 1)) * 256 + tid;

    float4 p = g_pxs[t];                       // sorted -> warp-coherent gathers
    float tx = p.x, ty = p.y, tz = p.z;
    int n = __float_as_int(p.w);

    float res[2 * GPC];

    #pragma unroll
    for (int j = 0; j < GPC; ++j) {
        int g = chunk * GPC + j;
        const float* m = sM + g * 16;
        float px = fmaf(m[0], tx, fmaf(m[1], ty, fmaf(m[2],  tz, m[3])));
        float py = fmaf(m[4], tx, fmaf(m[5], ty, fmaf(m[6],  tz, m[7])));
        float pz = fmaf(m[8], tx, fmaf(m[9], ty, fmaf(m[10], tz, m[11])));

        float fx0 = floorf(px), fy0 = floorf(py), fz0 = floorf(pz);
        float fx = px - fx0, fy = py - fy0, fz = pz - fz0;
        int ix = (int)fx0, iy = (int)fy0, iz = (int)fz0;

        // x folded into chunk slots; y,z: masked weights + clamped rows.
        bool inx = ((unsigned)ix < 64u);
        float wx0 = inx ? (1.0f - fx) : ((ix == -1) ? fx : 0.0f);
        float wx1 = inx ? fx : 0.0f;
        int xc = min(max(ix, 0), 63);

        float wy0 = ((unsigned)iy       < 64u) ? (1.0f - fy) : 0.0f;
        float wy1 = ((unsigned)(iy + 1) < 64u) ? fy          : 0.0f;
        int iy0c = min(max(iy,     0), 63);
        int iy1c = min(max(iy + 1, 0), 63);

        float wz0 = ((unsigned)iz       < 64u) ? (1.0f - fz) * FINV : 0.0f;
        float wz1 = ((unsigned)(iz + 1) < 64u) ? fz          * FINV : 0.0f;
        int iz0c = min(max(iz,     0), 63);
        int iz1c = min(max(iz + 1, 0), 63);

        const uint2* gp = g_pk + (size_t)g * CELLS;
        int r00 = (iz0c * GS + iy0c) * GS + xc;
        int r01 = (iz0c * GS + iy1c) * GS + xc;
        int r10 = (iz1c * GS + iy0c) * GS + xc;
        int r11 = (iz1c * GS + iy1c) * GS + xc;

        uint2 c00 = ld64nc(gp + r00);
        uint2 c01 = ld64nc(gp + r01);
        uint2 c10 = ld64nc(gp + r10);
        uint2 c11 = ld64nc(gp + r11);

        float w00 = wz0 * wy0, w01 = wz0 * wy1;
        float w10 = wz1 * wy0, w11 = wz1 * wy1;

        float a0 = 0.0f, a1 = 0.0f;
        {
            float2 s0 = __half22float2(*reinterpret_cast<__half2*>(&c00.x));
            float2 s1 = __half22float2(*reinterpret_cast<__half2*>(&c00.y));
            a0 = fmaf(s0.x, w00 * wx0, fmaf(s1.x, w00 * wx1, a0));
            a1 = fmaf(s0.y, w00 * wx0, fmaf(s1.y, w00 * wx1, a1));
        }
        {
            float2 s0 = __half22float2(*reinterpret_cast<__half2*>(&c01.x));
            float2 s1 = __half22float2(*reinterpret_cast<__half2*>(&c01.y));
            a0 = fmaf(s0.x, w01 * wx0, fmaf(s1.x, w01 * wx1, a0));
            a1 = fmaf(s0.y, w01 * wx0, fmaf(s1.y, w01 * wx1, a1));
        }
        {
            float2 s0 = __half22float2(*reinterpret_cast<__half2*>(&c10.x));
            float2 s1 = __half22float2(*reinterpret_cast<__half2*>(&c10.y));
            a0 = fmaf(s0.x, w10 * wx0, fmaf(s1.x, w10 * wx1, a0));
            a1 = fmaf(s0.y, w10 * wx0, fmaf(s1.y, w10 * wx1, a1));
        }
        {
            float2 s0 = __half22float2(*reinterpret_cast<__half2*>(&c11.x));
            float2 s1 = __half22float2(*reinterpret_cast<__half2*>(&c11.y));
            a0 = fmaf(s0.x, w11 * wx0, fmaf(s1.x, w11 * wx1, a0));
            a1 = fmaf(s0.y, w11 * wx0, fmaf(s1.y, w11 * wx1, a1));
        }

        res[2 * j]     = a0;
        res[2 * j + 1] = a1;
    }

    float* op = out + (size_t)n * (NGRIDS * 2) + chunk * (GPC * 2);
    st256cs_f(op, res);
    st256cs_f(op + 8, res + 8);
}

extern "C" void kernel_launch(void* const* d_in, const int* in_sizes, int n_in,
                              void* d_out, int out_size)
{
    const float* xs = (const float*)d_in[0];   // [262144, 3]
    const float* M  = (const float*)d_in[1];   // [64, 4, 4]
    const float* fg = (const float*)d_in[2];   // [64, 2, 64, 64, 64]
    float* out = (float*)d_out;                // [262144, 128]

    zero_kernel   <<<NBINS / 256, 256>>>();
    hist_kernel   <<<NPTS / 256, 256>>>(xs);
    scan1_kernel  <<<NBINS / 256, 256>>>();
    scan2_kernel  <<<1, 1024>>>();
    scan3_kernel  <<<NBINS / 256, 256>>>();
    scatter_kernel<<<NPTS / 256, 256>>>(xs);
    repack_kernel <<<(NGRIDS * CELLS) / 256, 256>>>(fg);
    sample_kernel <<<NCHUNK * PBLK, 256>>>(M, out);
}